// round 12
// baseline (speedup 1.0000x reference)
#include <cuda_runtime.h>
#include <cuda_bf16.h>
#include <cstdint>
#include <math.h>

#define N_IN   8192
#define N_MC   32768
#define K_TOP  656
#define MASK_WORDS (N_IN / 32)          // 256
#define NW     8                        // warps per block
#define HPAD   257                      // bank-rotating pad
#define HBINS  65536                    // top-16-bit histogram (64 rows x 1024)

__device__ float    g_overlap[N_MC];
__device__ uint32_t g_hist16[HBINS];    // zero at load; blocks RED, last block
                                        // consumes and re-zeros each launch
__device__ uint32_t g_done;             // drain ticket; last block resets to 0

__device__ __forceinline__ uint32_t warp_incl_scan(uint32_t v) {
    #pragma unroll
    for (int off = 1; off < 32; off <<= 1) {
        uint32_t u = __shfl_up_sync(0xffffffffu, v, off);
        if ((threadIdx.x & 31) >= off) v += u;
    }
    return v;
}

// ---------------------------------------------------------------------------
// Single fused kernel, 256 threads/block, 5 blocks/SM (40 warps -> high MLP):
//  * all blocks: mask build + 8 overlap rows + RED into global top16 histogram
//  * LAST block (drain ticket): exact top-K select + marking with 8 warps
//    (jax.lax.top_k tie semantics: threshold ties lowest-index-first)
// ---------------------------------------------------------------------------
__global__ __launch_bounds__(256, 5) void spatial_pooler_kernel(
    const float* __restrict__ I,
    const float* __restrict__ perm,
    const float* __restrict__ duty,
    const float* __restrict__ navg,
    float* __restrict__ out)
{
    __shared__ uint32_t smask[MASK_WORDS];
    __shared__ uint32_t s_hist[NW][HPAD];
    __shared__ uint32_t s_red[256];
    __shared__ uint32_t s_row[64];
    __shared__ uint32_t s_rowcp[1024];
    __shared__ uint32_t s_gs[32];
    __shared__ uint32_t s_wtot[NW];
    __shared__ uint32_t s_prefix;
    __shared__ int      s_rem;
    __shared__ int      s_rowpick;
    __shared__ int      s_need;
    __shared__ int      s_islast;

    const int tid  = threadIdx.x;
    const int wid  = tid >> 5;
    const int lane = tid & 31;

    // ---------------- overlap phase (all blocks) ----------------
    #pragma unroll
    for (int k2 = 0; k2 < 32; ++k2) {
        float v = I[k2 * 256 + tid];
        unsigned ball = __ballot_sync(0xffffffffu, v != 0.0f);
        if (lane == 0) smask[k2 * 8 + wid] = ball;
    }
    __syncthreads();

    {
        const int row = blockIdx.x * NW + wid;
        const float4* p = reinterpret_cast<const float4*>(perm + (size_t)row * N_IN);

        int cnt = 0;
        #pragma unroll 8
        for (int it = 0; it < 64; ++it) {
            int c4 = it * 32 + lane;
            float4 v = __ldcs(&p[c4]);           // streaming, evict-first
            int c = c4 * 4;
            uint32_t m = smask[c >> 5] >> (c & 31);
            cnt += ((m & 1u) && v.x >= 0.5f);
            cnt += ((m & 2u) && v.y >= 0.5f);
            cnt += ((m & 4u) && v.z >= 0.5f);
            cnt += ((m & 8u) && v.w >= 0.5f);
        }
        cnt = __reduce_add_sync(0xffffffffu, cnt);

        if (lane == 0) {
            float d = navg[row] - duty[row];
            float boost = (float)exp((double)d); // correctly-rounded f32 exp
            float val = boost * (float)cnt;
            g_overlap[row] = val;
            atomicAdd(&g_hist16[__float_as_uint(val) >> 16], 1u);
        }
    }

    // ---------------- drain ticket ----------------
    __threadfence();                             // publish rows + hist REDs
    if (tid == 0) {
        uint32_t ticket = atomicAdd(&g_done, 1u);
        int last = (ticket == gridDim.x - 1);
        if (last) g_done = 0;                    // reset for next graph replay
        s_islast = last;
    }
    __syncthreads();
    if (!s_islast) return;

    // ================ top-K phase (last block, 8 warps) ================
    const int seg = wid << 12;                   // warp's 4096-key segment

    // zero radix banks
    for (int z = tid; z < NW * HPAD; z += 256)
        ((uint32_t*)s_hist)[z] = 0u;

    // ---- phase 1, step A: row sums (warp w -> rows [8w, 8w+8)), uint4 ----
    #pragma unroll
    for (int rr = 0; rr < 8; ++rr) {
        int r = wid * 8 + rr;
        const uint4* hp = reinterpret_cast<const uint4*>(&g_hist16[r * 1024]);
        uint32_t s = 0;
        #pragma unroll
        for (int j = 0; j < 8; ++j) {            // 256 uint4 per row
            uint4 v = hp[j * 32 + lane];
            s += v.x + v.y + v.z + v.w;
        }
        s = __reduce_add_sync(0xffffffffu, s);
        if (lane == 0) s_row[r] = s;
    }
    __syncthreads();

    // ---- step B: warp 0 suffix-scans rows descending, picks row ----
    if (wid == 0) {
        uint32_t d0 = s_row[63 - lane];
        uint32_t d1 = s_row[31 - lane];
        uint32_t i0 = warp_incl_scan(d0);
        uint32_t tot0 = __shfl_sync(0xffffffffu, i0, 31);
        uint32_t i1 = warp_incl_scan(d1) + tot0;
        uint32_t e0 = i0 - d0, e1 = i1 - d1;
        if (e0 < K_TOP && i0 >= K_TOP) { s_rowpick = 63 - lane; s_need = K_TOP - (int)e0; }
        if (e1 < K_TOP && i1 >= K_TOP) { s_rowpick = 31 - lane; s_need = K_TOP - (int)e1; }
    }
    __syncthreads();

    // ---- step C1: copy threshold row to shared (uint4 burst) ----
    const int rpick = s_rowpick;
    reinterpret_cast<uint4*>(s_rowcp)[tid] =
        reinterpret_cast<const uint4*>(&g_hist16[rpick * 1024])[tid];
    __syncthreads();

    // re-zero global hist (uint4 stores; 16384 uint4 / 256 threads)
    {
        uint4 z4 = make_uint4(0u, 0u, 0u, 0u);
        uint4* hz = reinterpret_cast<uint4*>(g_hist16);
        #pragma unroll
        for (int j = 0; j < 64; ++j)
            hz[j * 256 + tid] = z4;
    }

    // ---- step C2: group sums (warp w -> groups {w, w+8, w+16, w+24}) ----
    #pragma unroll
    for (int g = 0; g < 4; ++g) {
        int grp = wid + g * NW;
        uint32_t v = s_rowcp[grp * 32 + lane];
        v = __reduce_add_sync(0xffffffffu, v);
        if (lane == 0) s_gs[grp] = v;
    }
    __syncthreads();

    // ---- step C3: warp 0 finds threshold column from shared ----
    if (wid == 0) {
        uint32_t dg = s_gs[31 - lane];
        uint32_t ginc = warp_incl_scan(dg);
        uint32_t gexcl = ginc - dg;
        int need = s_need;
        bool gc = ((int)gexcl < need && (int)ginc >= need);
        unsigned gb = __ballot_sync(0xffffffffu, gc);
        int glane = __ffs(gb) - 1;
        int gstar = 31 - glane;
        int need2 = need - (int)__shfl_sync(0xffffffffu, gexcl, glane);

        uint32_t h = s_rowcp[gstar * 32 + (31 - lane)];
        uint32_t inc = warp_incl_scan(h);
        bool cc = ((int)(inc - h) < need2 && (int)inc >= need2);
        if (cc) {                                // exactly one lane
            int col = gstar * 32 + (31 - lane);
            s_prefix = (uint32_t)(rpick * 1024 + col) << 16;
            s_rem = need2 - (int)(inc - h);
        }
    }
    __syncthreads();

    // ---- phase 2: two 8-bit radix passes (keys reloaded, 128 per thread) ----
    for (int shift = 8; shift >= 0; shift -= 8) {
        const uint32_t prefix = s_prefix;

        for (int i = 0; i < 128; ++i) {
            uint32_t k = __float_as_uint(g_overlap[seg + i * 32 + lane]);
            bool cand = (((k ^ prefix) >> (shift + 8)) == 0u);
            unsigned amask = __ballot_sync(0xffffffffu, cand);
            if (cand) {
                uint32_t bin = (k >> shift) & 255u;
                unsigned peers = __match_any_sync(amask, bin);
                if (lane == (__ffs(peers) - 1))
                    atomicAdd(&s_hist[wid][bin], (uint32_t)__popc(peers));
            }
        }
        __syncthreads();

        // reduce 8 banks -> s_red[bin] (all 256 threads, conflict-free)
        {
            uint32_t sum = 0;
            #pragma unroll
            for (int w = 0; w < NW; ++w) sum += s_hist[w][tid];
            s_red[tid] = sum;
        }
        __syncthreads();

        if (wid == 0) {
            uint32_t loc[8];
            uint32_t csum = 0;
            #pragma unroll
            for (int j = 0; j < 8; ++j) {
                loc[j] = s_red[255 - (lane * 8 + j)];
                csum += loc[j];
            }
            uint32_t winc = warp_incl_scan(csum);
            uint32_t wexcl = winc - csum;
            int rem = s_rem;
            if ((int)wexcl < rem && (int)winc >= rem) {
                uint32_t cum = wexcl;
                #pragma unroll
                for (int j = 0; j < 8; ++j) {
                    cum += loc[j];
                    if ((int)cum >= rem) {
                        uint32_t b = (uint32_t)(255 - (lane * 8 + j));
                        s_prefix = prefix | (b << shift);
                        s_rem = rem - (int)(cum - loc[j]);
                        break;
                    }
                }
            }
        } else if (shift == 8) {
            // warps 1..7 zero banks for the second pass
            for (int z = tid - 32; z < NW * HPAD; z += 224)
                ((uint32_t*)s_hist)[z] = 0u;
        }
        __syncthreads();
    }

    const uint32_t T = s_prefix;   // exact K-th largest key
    const int      r = s_rem;      // # of ==T entries to keep (lowest index)

    // ---- phase 3: marking (keys reloaded; count, scan, mark) ----
    int weq = 0;
    for (int i = 0; i < 128; ++i) {
        uint32_t k = __float_as_uint(g_overlap[seg + i * 32 + lane]);
        weq += __popc(__ballot_sync(0xffffffffu, k == T));
    }
    if (lane == 0) s_wtot[wid] = (uint32_t)weq;
    __syncthreads();

    if (wid == 0) {
        uint32_t v = (lane < NW) ? s_wtot[lane] : 0u;
        v = warp_incl_scan(v);
        if (lane < NW) s_wtot[lane] = v;         // inclusive over 8 warps
    }
    __syncthreads();

    int rank = (wid == 0) ? 0 : (int)s_wtot[wid - 1];
    for (int i = 0; i < 128; ++i) {
        uint32_t k = __float_as_uint(g_overlap[seg + i * 32 + lane]);
        bool eq = (k == T);
        unsigned ball = __ballot_sync(0xffffffffu, eq);
        int myrank = rank + __popc(ball & ((1u << lane) - 1u));
        out[seg + i * 32 + lane] = ((k > T) || (eq && myrank < r)) ? 1.0f : 0.0f;
        rank += __popc(ball);
    }
}

// ---------------------------------------------------------------------------
extern "C" void kernel_launch(void* const* d_in, const int* in_sizes, int n_in,
                              void* d_out, int out_size)
{
    const float* I    = (const float*)d_in[0];
    const float* perm = (const float*)d_in[1];
    const float* duty = (const float*)d_in[2];
    const float* navg = (const float*)d_in[3];
    float* out = (float*)d_out;

    (void)in_sizes; (void)n_in; (void)out_size;

    spatial_pooler_kernel<<<N_MC / NW, 256>>>(I, perm, duty, navg, out);
}

// round 13
// speedup vs baseline: 1.3829x; 1.3829x over previous
#include <cuda_runtime.h>
#include <cuda_bf16.h>
#include <cstdint>
#include <math.h>

#define N_IN   8192
#define N_MC   32768
#define K_TOP  656
#define MASK_WORDS (N_IN / 32)          // 256
#define HPAD   257                      // bank-rotating pad
#define HBINS  65536                    // top-16-bit histogram (64 rows x 1024)

__device__ float    g_overlap[N_MC];
__device__ uint32_t g_hist16[HBINS];    // zero at load; blocks RED, last block
                                        // consumes and re-zeros each launch
__device__ uint32_t g_done;             // drain ticket; last block resets to 0

__device__ __forceinline__ uint32_t warp_incl_scan(uint32_t v) {
    #pragma unroll
    for (int off = 1; off < 32; off <<= 1) {
        uint32_t u = __shfl_up_sync(0xffffffffu, v, off);
        if ((threadIdx.x & 31) >= off) v += u;
    }
    return v;
}

// ---------------------------------------------------------------------------
// Single fused kernel (R10 stream shape: 1024 thr, 1 blk/SM, 64 regs, MLP-8):
//  * all blocks: mask build + 32 overlap rows + RED into global top16 hist
//  * LAST block (drain ticket): exact top-K select + J*-cutoff marking
//    (jax.lax.top_k tie semantics: threshold ties lowest-index-first)
// ---------------------------------------------------------------------------
__global__ __launch_bounds__(1024) void spatial_pooler_kernel(
    const float* __restrict__ I,
    const float* __restrict__ perm,
    const float* __restrict__ duty,
    const float* __restrict__ navg,
    float* __restrict__ out)
{
    __shared__ uint32_t smask[MASK_WORDS];
    __shared__ uint32_t s_hist[32][HPAD];
    __shared__ uint32_t s_red[256];
    __shared__ uint32_t s_row[64];
    __shared__ uint32_t s_rowcp[1024];
    __shared__ uint32_t s_gs[32];
    __shared__ uint32_t s_wtot[32];
    __shared__ uint32_t s_prefix;
    __shared__ int      s_rem;
    __shared__ int      s_rowpick;
    __shared__ int      s_need;
    __shared__ int      s_islast;
    __shared__ int      s_jstar;

    const int tid  = threadIdx.x;
    const int wid  = tid >> 5;
    const int lane = tid & 31;

    // ---------------- overlap phase (all blocks) ----------------
    #pragma unroll
    for (int k2 = 0; k2 < 8; ++k2) {
        float v = I[k2 * 1024 + tid];
        unsigned ball = __ballot_sync(0xffffffffu, v != 0.0f);
        if (lane == 0) smask[k2 * 32 + wid] = ball;
    }
    __syncthreads();

    {
        const int row = blockIdx.x * 32 + wid;
        const float4* p = reinterpret_cast<const float4*>(perm + (size_t)row * N_IN);

        int cnt = 0;
        #pragma unroll 8
        for (int it = 0; it < 64; ++it) {
            int c4 = it * 32 + lane;
            float4 v = __ldcs(&p[c4]);           // streaming, evict-first
            int c = c4 * 4;
            uint32_t m = smask[c >> 5] >> (c & 31);
            cnt += ((m & 1u) && v.x >= 0.5f);
            cnt += ((m & 2u) && v.y >= 0.5f);
            cnt += ((m & 4u) && v.z >= 0.5f);
            cnt += ((m & 8u) && v.w >= 0.5f);
        }
        cnt = __reduce_add_sync(0xffffffffu, cnt);

        if (lane == 0) {
            float d = navg[row] - duty[row];
            float boost = (float)exp((double)d); // correctly-rounded f32 exp
            float val = boost * (float)cnt;
            g_overlap[row] = val;
            atomicAdd(&g_hist16[__float_as_uint(val) >> 16], 1u);
        }
    }

    // ---------------- drain ticket ----------------
    __threadfence();                             // publish rows + hist REDs
    if (tid == 0) {
        uint32_t ticket = atomicAdd(&g_done, 1u);
        int last = (ticket == gridDim.x - 1);
        if (last) g_done = 0;                    // reset for next graph replay
        s_islast = last;
    }
    __syncthreads();
    if (!s_islast) return;

    // ================ top-K phase (last block only) ================
    const int seg = wid << 10;

    // keys -> registers (L2-hot; overlaps >= 0 so u32 order == float order)
    uint32_t key[32];
    #pragma unroll
    for (int i = 0; i < 32; ++i)
        key[i] = __float_as_uint(g_overlap[seg + i * 32 + lane]);

    // zero radix banks (reused in phase 2)
    for (int z = tid; z < 32 * HPAD; z += 1024)
        ((uint32_t*)s_hist)[z] = 0u;

    // ---- phase 1, step A: row sums via uint4 (warp w -> rows {2w, 2w+1}) ----
    #pragma unroll
    for (int rr = 0; rr < 2; ++rr) {
        int r = wid * 2 + rr;
        const uint4* hp = reinterpret_cast<const uint4*>(&g_hist16[r * 1024]);
        uint32_t s = 0;
        #pragma unroll
        for (int j = 0; j < 8; ++j) {            // 256 uint4 per row
            uint4 v = hp[j * 32 + lane];
            s += v.x + v.y + v.z + v.w;
        }
        s = __reduce_add_sync(0xffffffffu, s);
        if (lane == 0) s_row[r] = s;
    }
    __syncthreads();

    // ---- step B: warp 0 suffix-scans rows descending, picks row ----
    if (wid == 0) {
        uint32_t d0 = s_row[63 - lane];
        uint32_t d1 = s_row[31 - lane];
        uint32_t i0 = warp_incl_scan(d0);
        uint32_t tot0 = __shfl_sync(0xffffffffu, i0, 31);
        uint32_t i1 = warp_incl_scan(d1) + tot0;
        uint32_t e0 = i0 - d0, e1 = i1 - d1;
        if (e0 < K_TOP && i0 >= K_TOP) { s_rowpick = 63 - lane; s_need = K_TOP - (int)e0; }
        if (e1 < K_TOP && i1 >= K_TOP) { s_rowpick = 31 - lane; s_need = K_TOP - (int)e1; }
    }
    __syncthreads();

    // ---- step C1: copy threshold row to shared (one coalesced burst) ----
    const int rpick = s_rowpick;
    s_rowcp[tid] = g_hist16[rpick * 1024 + tid];
    __syncthreads();

    // re-zero global hist for next launch (uint4, after all global reads)
    {
        uint4 z4 = make_uint4(0u, 0u, 0u, 0u);
        uint4* hz = reinterpret_cast<uint4*>(g_hist16);
        #pragma unroll
        for (int j = 0; j < 16; ++j)
            hz[j * 1024 + tid] = z4;
    }

    // ---- step C2: group sums (warp w -> cols [w*32, w*32+32)) ----
    {
        uint32_t v = s_rowcp[wid * 32 + lane];
        v = __reduce_add_sync(0xffffffffu, v);
        if (lane == 0) s_gs[wid] = v;
    }
    __syncthreads();

    // ---- step C3: warp 0 finds threshold column from shared ----
    if (wid == 0) {
        uint32_t dg = s_gs[31 - lane];
        uint32_t ginc = warp_incl_scan(dg);
        uint32_t gexcl = ginc - dg;
        int need = s_need;
        bool gc = ((int)gexcl < need && (int)ginc >= need);
        unsigned gb = __ballot_sync(0xffffffffu, gc);
        int glane = __ffs(gb) - 1;
        int gstar = 31 - glane;
        int need2 = need - (int)__shfl_sync(0xffffffffu, gexcl, glane);

        uint32_t h = s_rowcp[gstar * 32 + (31 - lane)];
        uint32_t inc = warp_incl_scan(h);
        bool cc = ((int)(inc - h) < need2 && (int)inc >= need2);
        if (cc) {                                // exactly one lane
            int col = gstar * 32 + (31 - lane);
            s_prefix = (uint32_t)(rpick * 1024 + col) << 16;
            s_rem = need2 - (int)(inc - h);
        }
    }
    __syncthreads();

    // ---- phase 2: two 8-bit radix passes over the low 16 bits ----
    for (int shift = 8; shift >= 0; shift -= 8) {
        const uint32_t prefix = s_prefix;

        #pragma unroll
        for (int i = 0; i < 32; ++i) {
            uint32_t k = key[i];
            bool cand = (((k ^ prefix) >> (shift + 8)) == 0u);
            unsigned amask = __ballot_sync(0xffffffffu, cand);
            if (cand) {
                uint32_t bin = (k >> shift) & 255u;
                unsigned peers = __match_any_sync(amask, bin);
                if (lane == (__ffs(peers) - 1))
                    atomicAdd(&s_hist[wid][bin], (uint32_t)__popc(peers));
            }
        }
        __syncthreads();

        if (tid < 256) {
            uint32_t sum = 0;
            #pragma unroll
            for (int w = 0; w < 32; ++w) sum += s_hist[w][tid];
            s_red[tid] = sum;
        }
        __syncthreads();

        if (wid == 0) {
            uint32_t loc[8];
            uint32_t csum = 0;
            #pragma unroll
            for (int j = 0; j < 8; ++j) {
                loc[j] = s_red[255 - (lane * 8 + j)];
                csum += loc[j];
            }
            uint32_t winc = warp_incl_scan(csum);
            uint32_t wexcl = winc - csum;
            int rem = s_rem;
            if ((int)wexcl < rem && (int)winc >= rem) {
                uint32_t cum = wexcl;
                #pragma unroll
                for (int j = 0; j < 8; ++j) {
                    cum += loc[j];
                    if ((int)cum >= rem) {
                        uint32_t b = (uint32_t)(255 - (lane * 8 + j));
                        s_prefix = prefix | (b << shift);
                        s_rem = rem - (int)(cum - loc[j]);
                        break;
                    }
                }
            }
        } else if (shift == 8) {
            for (int z = tid - 32; z < 32 * HPAD; z += 992)
                ((uint32_t*)s_hist)[z] = 0u;
        }
        __syncthreads();
    }

    const uint32_t T = s_prefix;   // exact K-th largest key
    const int      r = s_rem;      // # of ==T entries to keep (lowest index)

    // ---- phase 3: find J* = index of the r-th tie (ascending), then mark ----
    int weq = 0;
    #pragma unroll
    for (int i = 0; i < 32; ++i)
        weq += __popc(__ballot_sync(0xffffffffu, key[i] == T));
    if (lane == 0) s_wtot[wid] = (uint32_t)weq;
    __syncthreads();

    if (wid == 0) s_wtot[lane] = warp_incl_scan(s_wtot[lane]);   // inclusive
    __syncthreads();

    {
        int wpre = (wid == 0) ? 0 : (int)s_wtot[wid - 1];
        int winc = (int)s_wtot[wid];
        if (wpre < r && winc >= r) {
            // this warp's segment contains the r-th tie; locate it
            int need = r - wpre;                 // 1-based within this warp
            int acc = 0;
            #pragma unroll
            for (int i = 0; i < 32; ++i) {
                unsigned ball = __ballot_sync(0xffffffffu, key[i] == T);
                int c = __popc(ball);
                if (acc + c >= need) {
                    // the (need-acc)-th set bit of ball, ascending lane order
                    int t2 = need - acc;
                    unsigned b = ball;
                    #pragma unroll
                    for (int q = 1; q < 32; ++q) {   // peel t2-1 lowest bits
                        if (q < t2) b &= b - 1u;
                    }
                    int l = __ffs(b) - 1;            // lane of r-th tie
                    if (lane == 0) s_jstar = seg + i * 32 + l + 1;  // exclusive
                    break;
                }
                acc += c;
            }
        }
        if (r == 0 && tid == 0) s_jstar = 0;     // degenerate: no ties kept
    }
    __syncthreads();

    const int jstar = s_jstar;
    #pragma unroll
    for (int i = 0; i < 32; ++i) {
        int j = seg + i * 32 + lane;
        uint32_t k = key[i];
        out[j] = ((k > T) || (k == T && j < jstar)) ? 1.0f : 0.0f;
    }
}

// ---------------------------------------------------------------------------
extern "C" void kernel_launch(void* const* d_in, const int* in_sizes, int n_in,
                              void* d_out, int out_size)
{
    const float* I    = (const float*)d_in[0];
    const float* perm = (const float*)d_in[1];
    const float* duty = (const float*)d_in[2];
    const float* navg = (const float*)d_in[3];
    float* out = (float*)d_out;

    (void)in_sizes; (void)n_in; (void)out_size;

    spatial_pooler_kernel<<<N_MC / 32, 1024>>>(I, perm, duty, navg, out);
}

// round 14
// speedup vs baseline: 1.3834x; 1.0003x over previous
#include <cuda_runtime.h>
#include <cuda_bf16.h>
#include <cstdint>
#include <math.h>

#define N_IN   8192
#define N_MC   32768
#define K_TOP  656
#define MASK_WORDS (N_IN / 32)          // 256
#define HPAD   257                      // bank-rotating pad
#define HBINS  65536                    // top-16-bit histogram (64 rows x 1024)
#define NBLK   148                      // persistent: one block per SM
#define ROWS_PER_TICKET 2
#define TICKETS (N_MC / ROWS_PER_TICKET)   // 16384
#define NWARPS  (NBLK * 32)                // 4736 static first tickets

__device__ float    g_overlap[N_MC];
__device__ uint32_t g_hist16[HBINS];    // zero at load; blocks RED, drain block
                                        // consumes and re-zeros each launch
__device__ uint32_t g_done;             // drain ticket; reset by drain block
__device__ uint32_t g_row;              // refill ticket counter; reset by drain

__device__ __forceinline__ uint32_t warp_incl_scan(uint32_t v) {
    #pragma unroll
    for (int off = 1; off < 32; off <<= 1) {
        uint32_t u = __shfl_up_sync(0xffffffffu, v, off);
        if ((threadIdx.x & 31) >= off) v += u;
    }
    return v;
}

// ---------------------------------------------------------------------------
// Persistent fused kernel (148 blocks, 1024 thr, 64 regs, unroll-8 stream):
//  * warps pull 2-row tickets (first ticket static, refills prefetched)
//  * rows: overlap_eff = exp(na-dc) * popcount((perm >= 0.5) & I), + hist RED
//  * drain block (after proper sync+fence): exact top-K + J*-cutoff marking
//    (jax.lax.top_k tie semantics: threshold ties lowest-index-first)
// ---------------------------------------------------------------------------
__global__ __launch_bounds__(1024) void spatial_pooler_kernel(
    const float* __restrict__ I,
    const float* __restrict__ perm,
    const float* __restrict__ duty,
    const float* __restrict__ navg,
    float* __restrict__ out)
{
    __shared__ uint32_t smask[MASK_WORDS];
    __shared__ uint32_t s_hist[32][HPAD];
    __shared__ uint32_t s_red[256];
    __shared__ uint32_t s_row[64];
    __shared__ uint32_t s_rowcp[1024];
    __shared__ uint32_t s_gs[32];
    __shared__ uint32_t s_wtot[32];
    __shared__ uint32_t s_prefix;
    __shared__ int      s_rem;
    __shared__ int      s_rowpick;
    __shared__ int      s_need;
    __shared__ int      s_islast;
    __shared__ int      s_jstar;

    const int tid  = threadIdx.x;
    const int wid  = tid >> 5;
    const int lane = tid & 31;

    // ---------------- mask build (once per block) ----------------
    #pragma unroll
    for (int k2 = 0; k2 < 8; ++k2) {
        float v = I[k2 * 1024 + tid];
        unsigned ball = __ballot_sync(0xffffffffu, v != 0.0f);
        if (lane == 0) smask[k2 * 32 + wid] = ball;
    }
    __syncthreads();

    // ---------------- streaming loop: per-warp 2-row tickets ----------------
    {
        uint32_t t = (uint32_t)(blockIdx.x * 32 + wid);   // static first ticket
        while (t < TICKETS) {
            uint32_t nt = 0xffffffffu;
            if (lane == 0) nt = NWARPS + atomicAdd(&g_row, 1u);  // prefetch

            #pragma unroll
            for (int rr = 0; rr < ROWS_PER_TICKET; ++rr) {
                const int row = (int)t * ROWS_PER_TICKET + rr;
                const float4* p =
                    reinterpret_cast<const float4*>(perm + (size_t)row * N_IN);

                int cnt = 0;
                #pragma unroll 8
                for (int it = 0; it < 64; ++it) {
                    int c4 = it * 32 + lane;
                    float4 v = __ldcs(&p[c4]);       // streaming, evict-first
                    int c = c4 * 4;
                    uint32_t m = smask[c >> 5] >> (c & 31);
                    cnt += ((m & 1u) && v.x >= 0.5f);
                    cnt += ((m & 2u) && v.y >= 0.5f);
                    cnt += ((m & 4u) && v.z >= 0.5f);
                    cnt += ((m & 8u) && v.w >= 0.5f);
                }
                cnt = __reduce_add_sync(0xffffffffu, cnt);

                if (lane == 0) {
                    float d = navg[row] - duty[row];
                    float boost = (float)exp((double)d);  // exact f32 exp
                    float val = boost * (float)cnt;
                    g_overlap[row] = val;
                    atomicAdd(&g_hist16[__float_as_uint(val) >> 16], 1u);
                }
            }
            t = __shfl_sync(0xffffffffu, nt, 0);
        }
    }

    // ---------------- drain ticket (race-free: sync BEFORE fence+ticket) ----
    __syncthreads();                     // all warps of this block done
    __threadfence();                     // publish this block's rows + REDs
    if (tid == 0) {
        uint32_t ticket = atomicAdd(&g_done, 1u);
        int last = (ticket == gridDim.x - 1);
        if (last) { g_done = 0; g_row = 0; }   // reset for next graph replay
        s_islast = last;
    }
    __syncthreads();
    if (!s_islast) return;
    __threadfence();                     // order ticket-read before tail reads

    // ================ top-K phase (drain block only) ================
    const int seg = wid << 10;

    // keys -> registers (overlaps >= 0 so u32 order == float order)
    uint32_t key[32];
    #pragma unroll
    for (int i = 0; i < 32; ++i)
        key[i] = __float_as_uint(g_overlap[seg + i * 32 + lane]);

    // zero radix banks (reused in phase 2)
    for (int z = tid; z < 32 * HPAD; z += 1024)
        ((uint32_t*)s_hist)[z] = 0u;

    // ---- phase 1, step A: row sums via uint4 (warp w -> rows {2w, 2w+1}) ----
    #pragma unroll
    for (int rr = 0; rr < 2; ++rr) {
        int r = wid * 2 + rr;
        const uint4* hp = reinterpret_cast<const uint4*>(&g_hist16[r * 1024]);
        uint32_t s = 0;
        #pragma unroll
        for (int j = 0; j < 8; ++j) {            // 256 uint4 per row
            uint4 v = hp[j * 32 + lane];
            s += v.x + v.y + v.z + v.w;
        }
        s = __reduce_add_sync(0xffffffffu, s);
        if (lane == 0) s_row[r] = s;
    }
    __syncthreads();

    // ---- step B: warp 0 suffix-scans rows descending, picks row ----
    if (wid == 0) {
        uint32_t d0 = s_row[63 - lane];
        uint32_t d1 = s_row[31 - lane];
        uint32_t i0 = warp_incl_scan(d0);
        uint32_t tot0 = __shfl_sync(0xffffffffu, i0, 31);
        uint32_t i1 = warp_incl_scan(d1) + tot0;
        uint32_t e0 = i0 - d0, e1 = i1 - d1;
        if (e0 < K_TOP && i0 >= K_TOP) { s_rowpick = 63 - lane; s_need = K_TOP - (int)e0; }
        if (e1 < K_TOP && i1 >= K_TOP) { s_rowpick = 31 - lane; s_need = K_TOP - (int)e1; }
    }
    __syncthreads();

    // ---- step C1: copy threshold row to shared (one coalesced burst) ----
    const int rpick = s_rowpick;
    s_rowcp[tid] = g_hist16[rpick * 1024 + tid];
    __syncthreads();

    // re-zero global hist for next launch (uint4, after all global reads)
    {
        uint4 z4 = make_uint4(0u, 0u, 0u, 0u);
        uint4* hz = reinterpret_cast<uint4*>(g_hist16);
        #pragma unroll
        for (int j = 0; j < 16; ++j)
            hz[j * 1024 + tid] = z4;
    }

    // ---- step C2: group sums (warp w -> cols [w*32, w*32+32)) ----
    {
        uint32_t v = s_rowcp[wid * 32 + lane];
        v = __reduce_add_sync(0xffffffffu, v);
        if (lane == 0) s_gs[wid] = v;
    }
    __syncthreads();

    // ---- step C3: warp 0 finds threshold column from shared ----
    if (wid == 0) {
        uint32_t dg = s_gs[31 - lane];
        uint32_t ginc = warp_incl_scan(dg);
        uint32_t gexcl = ginc - dg;
        int need = s_need;
        bool gc = ((int)gexcl < need && (int)ginc >= need);
        unsigned gb = __ballot_sync(0xffffffffu, gc);
        int glane = __ffs(gb) - 1;
        int gstar = 31 - glane;
        int need2 = need - (int)__shfl_sync(0xffffffffu, gexcl, glane);

        uint32_t h = s_rowcp[gstar * 32 + (31 - lane)];
        uint32_t inc = warp_incl_scan(h);
        bool cc = ((int)(inc - h) < need2 && (int)inc >= need2);
        if (cc) {                                // exactly one lane
            int col = gstar * 32 + (31 - lane);
            s_prefix = (uint32_t)(rpick * 1024 + col) << 16;
            s_rem = need2 - (int)(inc - h);
        }
    }
    __syncthreads();

    // ---- phase 2: two 8-bit radix passes over the low 16 bits ----
    for (int shift = 8; shift >= 0; shift -= 8) {
        const uint32_t prefix = s_prefix;

        #pragma unroll
        for (int i = 0; i < 32; ++i) {
            uint32_t k = key[i];
            bool cand = (((k ^ prefix) >> (shift + 8)) == 0u);
            unsigned amask = __ballot_sync(0xffffffffu, cand);
            if (cand) {
                uint32_t bin = (k >> shift) & 255u;
                unsigned peers = __match_any_sync(amask, bin);
                if (lane == (__ffs(peers) - 1))
                    atomicAdd(&s_hist[wid][bin], (uint32_t)__popc(peers));
            }
        }
        __syncthreads();

        if (tid < 256) {
            uint32_t sum = 0;
            #pragma unroll
            for (int w = 0; w < 32; ++w) sum += s_hist[w][tid];
            s_red[tid] = sum;
        }
        __syncthreads();

        if (wid == 0) {
            uint32_t loc[8];
            uint32_t csum = 0;
            #pragma unroll
            for (int j = 0; j < 8; ++j) {
                loc[j] = s_red[255 - (lane * 8 + j)];
                csum += loc[j];
            }
            uint32_t winc = warp_incl_scan(csum);
            uint32_t wexcl = winc - csum;
            int rem = s_rem;
            if ((int)wexcl < rem && (int)winc >= rem) {
                uint32_t cum = wexcl;
                #pragma unroll
                for (int j = 0; j < 8; ++j) {
                    cum += loc[j];
                    if ((int)cum >= rem) {
                        uint32_t b = (uint32_t)(255 - (lane * 8 + j));
                        s_prefix = prefix | (b << shift);
                        s_rem = rem - (int)(cum - loc[j]);
                        break;
                    }
                }
            }
        } else if (shift == 8) {
            for (int z = tid - 32; z < 32 * HPAD; z += 992)
                ((uint32_t*)s_hist)[z] = 0u;
        }
        __syncthreads();
    }

    const uint32_t T = s_prefix;   // exact K-th largest key
    const int      r = s_rem;      // # of ==T entries to keep (lowest index)

    // ---- phase 3: find J* = index of the r-th tie (ascending), then mark ----
    int weq = 0;
    #pragma unroll
    for (int i = 0; i < 32; ++i)
        weq += __popc(__ballot_sync(0xffffffffu, key[i] == T));
    if (lane == 0) s_wtot[wid] = (uint32_t)weq;
    __syncthreads();

    if (wid == 0) s_wtot[lane] = warp_incl_scan(s_wtot[lane]);   // inclusive
    __syncthreads();

    {
        int wpre = (wid == 0) ? 0 : (int)s_wtot[wid - 1];
        int winc = (int)s_wtot[wid];
        if (wpre < r && winc >= r) {
            int need = r - wpre;                 // 1-based within this warp
            int acc = 0;
            #pragma unroll
            for (int i = 0; i < 32; ++i) {
                unsigned ball = __ballot_sync(0xffffffffu, key[i] == T);
                int c = __popc(ball);
                if (acc + c >= need) {
                    int t2 = need - acc;
                    unsigned b = ball;
                    #pragma unroll
                    for (int q = 1; q < 32; ++q) {
                        if (q < t2) b &= b - 1u;
                    }
                    int l = __ffs(b) - 1;        // lane of the r-th tie
                    if (lane == 0) s_jstar = seg + i * 32 + l + 1;  // exclusive
                    break;
                }
                acc += c;
            }
        }
        if (r == 0 && tid == 0) s_jstar = 0;
    }
    __syncthreads();

    const int jstar = s_jstar;
    #pragma unroll
    for (int i = 0; i < 32; ++i) {
        int j = seg + i * 32 + lane;
        uint32_t k = key[i];
        out[j] = ((k > T) || (k == T && j < jstar)) ? 1.0f : 0.0f;
    }
}

// ---------------------------------------------------------------------------
extern "C" void kernel_launch(void* const* d_in, const int* in_sizes, int n_in,
                              void* d_out, int out_size)
{
    const float* I    = (const float*)d_in[0];
    const float* perm = (const float*)d_in[1];
    const float* duty = (const float*)d_in[2];
    const float* navg = (const float*)d_in[3];
    float* out = (float*)d_out;

    (void)in_sizes; (void)n_in; (void)out_size;

    spatial_pooler_kernel<<<NBLK, 1024>>>(I, perm, duty, navg, out);
}